// round 1
// baseline (speedup 1.0000x reference)
#include <cuda_runtime.h>
#include <math.h>

#define S_LEN 512
#define BATCH 64
#define IN_SZ 256
#define HID   1024
#define NCTA  128
#define CPC   8            // columns per CTA = HID/NCTA
#define TPB   256

// ---------------- scratch / barrier state (no allocs allowed) ----------------
__device__ float    g_xv[(size_t)S_LEN * BATCH * HID];   // 128 MB scratch: x@V + b + b2
__device__ unsigned g_count = 0;   // barrier arrivals (monotone across replays)
__device__ unsigned g_phase = 0;   // barrier generation (monotone across replays)

// ---------------- software grid barrier (128 co-resident CTAs) ---------------
__device__ __forceinline__ void grid_sync(unsigned target) {
    __syncthreads();
    if (threadIdx.x == 0) {
        unsigned ticket;
        asm volatile("atom.add.acq_rel.gpu.u32 %0, [%1], 1;"
                     : "=r"(ticket) : "l"(&g_count) : "memory");
        if ((ticket & (NCTA - 1)) == (NCTA - 1)) {
            asm volatile("red.add.release.gpu.u32 [%0], 1;"
                         :: "l"(&g_phase) : "memory");
        } else {
            unsigned p;
            do {
                asm volatile("ld.acquire.gpu.u32 %0, [%1];"
                             : "=r"(p) : "l"(&g_phase) : "memory");
            } while ((int)(p - target) < 0);
        }
    }
    __syncthreads();
}

// ---------------- cp.async helpers ----------------
__device__ __forceinline__ void cp_async16(float* smem_dst, const float* gsrc) {
    unsigned s = (unsigned)__cvta_generic_to_shared(smem_dst);
    asm volatile("cp.async.cg.shared.global [%0], [%1], 16;" :: "r"(s), "l"(gsrc));
}
__device__ __forceinline__ void cp_commit() {
    asm volatile("cp.async.commit_group;");
}
template <int N> __device__ __forceinline__ void cp_wait() {
    asm volatile("cp.async.wait_group %0;" :: "n"(N));
}

// =============================================================================
// Phase 1: xv[m][n] = X[m][:] @ V[:][n] + b[n] + b2[n],  M=32768, N=1024, K=256
// 128x128 block tile, BK=16, 256 threads, 8x8 register tile.
// =============================================================================
__global__ __launch_bounds__(TPB)
void xv_gemm(const float* __restrict__ X, const float* __restrict__ V,
             const float* __restrict__ b1, const float* __restrict__ b2) {
    __shared__ float As[16][132];   // [k][m] transposed, padded
    __shared__ float Bs[16][132];   // [k][n], padded

    const int tid = threadIdx.x;
    const int m0  = blockIdx.y * 128;
    const int n0  = blockIdx.x * 128;
    const int ty  = tid >> 4;       // 0..15  (m sub-tile)
    const int tx  = tid & 15;       // 0..15  (n sub-tile)

    float acc[8][8];
    #pragma unroll
    for (int i = 0; i < 8; i++)
        #pragma unroll
        for (int j = 0; j < 8; j++) acc[i][j] = 0.f;

    for (int k0 = 0; k0 < IN_SZ; k0 += 16) {
        // A tile: 128x16, load float4 along k, store transposed
        #pragma unroll
        for (int i = 0; i < 2; i++) {
            int lin = i * 256 + tid;          // 0..511
            int row = lin >> 2, q = lin & 3;
            float4 v = *(const float4*)(X + (size_t)(m0 + row) * IN_SZ + k0 + q * 4);
            As[q * 4 + 0][row] = v.x;
            As[q * 4 + 1][row] = v.y;
            As[q * 4 + 2][row] = v.z;
            As[q * 4 + 3][row] = v.w;
        }
        // B tile: 16x128
        #pragma unroll
        for (int i = 0; i < 2; i++) {
            int lin  = i * 256 + tid;         // 0..511
            int krow = lin >> 5, c4 = lin & 31;
            *(float4*)&Bs[krow][c4 * 4] =
                *(const float4*)(V + (size_t)(k0 + krow) * HID + n0 + c4 * 4);
        }
        __syncthreads();
        #pragma unroll
        for (int k = 0; k < 16; k++) {
            float a[8], bb[8];
            *(float4*)&a[0]  = *(float4*)&As[k][ty * 8];
            *(float4*)&a[4]  = *(float4*)&As[k][ty * 8 + 4];
            *(float4*)&bb[0] = *(float4*)&Bs[k][tx * 8];
            *(float4*)&bb[4] = *(float4*)&Bs[k][tx * 8 + 4];
            #pragma unroll
            for (int i = 0; i < 8; i++)
                #pragma unroll
                for (int j = 0; j < 8; j++)
                    acc[i][j] = fmaf(a[i], bb[j], acc[i][j]);
        }
        __syncthreads();
    }

    float bsum[8];
    #pragma unroll
    for (int j = 0; j < 8; j++)
        bsum[j] = b1[n0 + tx * 8 + j] + b2[n0 + tx * 8 + j];

    #pragma unroll
    for (int i = 0; i < 8; i++) {
        float* dst = g_xv + (size_t)(m0 + ty * 8 + i) * HID + n0 + tx * 8;
        float4 v0 = make_float4(acc[i][0] + bsum[0], acc[i][1] + bsum[1],
                                acc[i][2] + bsum[2], acc[i][3] + bsum[3]);
        float4 v1 = make_float4(acc[i][4] + bsum[4], acc[i][5] + bsum[5],
                                acc[i][6] + bsum[6], acc[i][7] + bsum[7]);
        *(float4*)dst       = v0;
        *(float4*)(dst + 4) = v1;
    }
}

// =============================================================================
// Phase 2: persistent recurrence. 128 CTAs x 256 threads.
// CTA owns 8 columns of W, pinned in smem for all 512 steps.
// Per step: stream h_{t-1} (from d_out) in 64x128 chunks (double-buffered
// cp.async), each thread computes 2 outputs (one batch row, 2 columns),
// tanh, store to d_out (which is the h history), grid barrier.
// =============================================================================
__global__ __launch_bounds__(TPB)
void rnn_persistent(const float* __restrict__ W, float* out) {
    extern __shared__ float sm[];
    float* Ws  = sm;                 // [8][1028]  (pad 4 -> conflict-free)
    float* Hs0 = sm + 8 * 1028;      // 2 x [64][132]
    const int HS_STRIDE = 64 * 132;  // floats per buffer

    const int tid   = threadIdx.x;
    const int cbase = blockIdx.x * CPC;

    // Load W slice once: Ws[c][k] = W[k][cbase+c]. warp w handles column w.
    {
        int w = tid >> 5, lane = tid & 31;
        for (int k = lane; k < HID; k += 32)
            Ws[w * 1028 + k] = W[(size_t)k * HID + cbase + w];
    }

    // Snapshot barrier phase (stable at launch; monotone across graph replays)
    __shared__ unsigned s_base;
    if (tid == 0) {
        unsigned p;
        asm volatile("ld.acquire.gpu.u32 %0, [%1];" : "=r"(p) : "l"(&g_phase) : "memory");
        s_base = p;
    }
    __syncthreads();
    const unsigned base = s_base;

    const int b  = tid >> 2;         // 0..63  batch row
    const int cg = tid & 3;          // 0..3
    const int c0 = cg * 2;           // two adjacent columns

    const float* w0p = Ws + (c0 + 0) * 1028;
    const float* w1p = Ws + (c0 + 1) * 1028;
    const float* h4p = Hs0 + b * 132;   // per-buffer base added below

    for (int t = 0; t < S_LEN; t++) {
        // prefetch xv for this step early
        const float* xvp = g_xv + (size_t)t * BATCH * HID + (size_t)b * HID + cbase;
        float xv0 = xvp[c0], xv1 = xvp[c0 + 1];

        float acc0 = 0.f, acc1 = 0.f;

        if (t > 0) {
            const float* prev = out + (size_t)(t - 1) * BATCH * HID;

            // prologue: chunk 0 -> buf 0
            #pragma unroll
            for (int i = 0; i < 8; i++) {
                int lin = i * 256 + tid;
                int row = lin >> 5, col4 = lin & 31;
                cp_async16(Hs0 + row * 132 + col4 * 4,
                           prev + (size_t)row * HID + col4 * 4);
            }
            cp_commit();

            #pragma unroll 1
            for (int c = 0; c < 8; c++) {
                const int kc = c * 128;
                if (c < 7) {
                    float* nb = Hs0 + ((c + 1) & 1) * HS_STRIDE;
                    const int nkc = kc + 128;
                    #pragma unroll
                    for (int i = 0; i < 8; i++) {
                        int lin = i * 256 + tid;
                        int row = lin >> 5, col4 = lin & 31;
                        cp_async16(nb + row * 132 + col4 * 4,
                                   prev + (size_t)row * HID + nkc + col4 * 4);
                    }
                    cp_commit();
                    cp_wait<1>();   // chunk c has landed
                } else {
                    cp_wait<0>();
                }
                __syncthreads();

                const float* H = h4p + (c & 1) * HS_STRIDE;
                const float* wa = w0p + kc;
                const float* wb = w1p + kc;
                #pragma unroll
                for (int k4 = 0; k4 < 32; k4++) {
                    float4 h  = *(const float4*)(H  + k4 * 4);
                    float4 wx = *(const float4*)(wa + k4 * 4);
                    float4 wy = *(const float4*)(wb + k4 * 4);
                    acc0 = fmaf(h.x, wx.x, acc0);
                    acc0 = fmaf(h.y, wx.y, acc0);
                    acc0 = fmaf(h.z, wx.z, acc0);
                    acc0 = fmaf(h.w, wx.w, acc0);
                    acc1 = fmaf(h.x, wy.x, acc1);
                    acc1 = fmaf(h.y, wy.y, acc1);
                    acc1 = fmaf(h.z, wy.z, acc1);
                    acc1 = fmaf(h.w, wy.w, acc1);
                }
                __syncthreads();   // protect buffer before next overwrite
            }
        }

        float o0 = tanhf(acc0 + xv0);
        float o1 = tanhf(acc1 + xv1);

        float* dst = out + (size_t)t * BATCH * HID + (size_t)b * HID + cbase;
        *(float2*)(dst + c0) = make_float2(o0, o1);
        if (t == S_LEN - 1) {
            float* dst2 = out + (size_t)S_LEN * BATCH * HID + (size_t)b * HID + cbase;
            *(float2*)(dst2 + c0) = make_float2(o0, o1);
        }

        grid_sync(base + (unsigned)t + 1u);   // write(t) visible before read(t+1)
    }
}

// =============================================================================
// launch
// =============================================================================
extern "C" void kernel_launch(void* const* d_in, const int* in_sizes, int n_in,
                              void* d_out, int out_size) {
    const float* x  = (const float*)d_in[0];
    const float* V  = (const float*)d_in[1];
    const float* W  = (const float*)d_in[2];
    const float* b  = (const float*)d_in[3];
    const float* b2 = (const float*)d_in[4];
    float* out = (float*)d_out;

    // Phase 1: input projection for all timesteps
    dim3 g1(HID / 128, (S_LEN * BATCH) / 128);
    xv_gemm<<<g1, TPB>>>(x, V, b, b2);

    // Phase 2: persistent recurrence
    const int smem_bytes = (8 * 1028 + 2 * 64 * 132) * (int)sizeof(float); // 100480
    cudaFuncSetAttribute(rnn_persistent,
                         cudaFuncAttributeMaxDynamicSharedMemorySize, smem_bytes);
    rnn_persistent<<<NCTA, TPB, smem_bytes>>>(W, out);
}